// round 16
// baseline (speedup 1.0000x reference)
#include <cuda_runtime.h>
#include <math.h>
#include <float.h>

#define NN 50000
#define EE 400000
#define DH 128
#define DE 32
#define NH 8
#define CH 16

typedef unsigned long long ull;

// ---------------- scratch (device globals: no allocation allowed) ----------------
__device__ float g_q[(size_t)NN * DH];
__device__ float g_k[(size_t)NN * DH];
__device__ float g_v[(size_t)NN * DH];
__device__ float g_agg[(size_t)NN * DH];        // skip projection per layer
__device__ float g_feat[(size_t)NN * DH];
__device__ float g_qwe[(size_t)NN * NH * DE];   // qWe[n][h][j] = sum_c q[n,hc]*We[hc][j]
__device__ float g_raw[(size_t)EE * NH];        // raw logits (orig edge order)
__device__ float g_m[(size_t)NN * NH];          // per-(node,head) softmax max
__device__ float g_s[(size_t)NN * NH];          // per-(node,head) softmax sum
// CSR (built once per call)
__device__ int g_deg[NN];
__device__ int g_fill[NN];
__device__ int g_rowptr[NN + 1];
__device__ int g_eperm[EE];

// ---------------- packed f32x2 helpers (2x fp32 FMA rate on sm_103a) -------------
__device__ __forceinline__ ull pk2(float lo, float hi) {
    ull r; asm("mov.b64 %0, {%1, %2};" : "=l"(r) : "f"(lo), "f"(hi)); return r;
}
__device__ __forceinline__ float2 upk2(ull a) {
    float2 r; asm("mov.b64 {%0, %1}, %2;" : "=f"(r.x), "=f"(r.y) : "l"(a)); return r;
}
__device__ __forceinline__ ull ffma2(ull a, ull b, ull c) {
    ull d; asm("fma.rn.f32x2 %0, %1, %2, %3;" : "=l"(d) : "l"(a), "l"(b), "l"(c)); return d;
}

// ---------------- fused 4-way node projection GEMM --------------------------------
#define BN 64
#define WPAD 132
#define PROJ_THREADS 256
#define PROJ_SMEM ((BN * DH + DH * WPAD) * 4)

__global__ void proj_kernel(const float* __restrict__ hin,
                            const float* __restrict__ Wq, const float* __restrict__ bq,
                            const float* __restrict__ Wk, const float* __restrict__ bk,
                            const float* __restrict__ Wv, const float* __restrict__ bv,
                            const float* __restrict__ Ws, const float* __restrict__ bs) {
    extern __shared__ float sh[];
    float* xs  = sh;             // [BN][DH]
    float* wsT = sh + BN * DH;   // [DH][WPAD]
    const int tid = threadIdx.x;
    const int node0 = blockIdx.x * BN;

    for (int i = tid; i < BN * DH / 4; i += PROJ_THREADS) {
        int n  = i / (DH / 4);
        int c4 = (i % (DH / 4)) * 4;
        float4 v = make_float4(0.f, 0.f, 0.f, 0.f);
        if (node0 + n < NN) v = *(const float4*)(hin + (size_t)(node0 + n) * DH + c4);
        *(float4*)(xs + n * DH + c4) = v;
    }

    const int cgrp = tid & 31;
    const int ngrp = tid >> 5;
    const int c0 = cgrp * 4;

    const float* Wlist[4] = {Wq, Wk, Wv, Ws};
    const float* Blist[4] = {bq, bk, bv, bs};
    float* Olist[4] = {g_q, g_k, g_v, g_agg};

    for (int w = 0; w < 4; ++w) {
        __syncthreads();
        const float* W = Wlist[w];
        for (int t = tid; t < DH * DH; t += PROJ_THREADS) {
            int ch = t >> 7, kk = t & (DH - 1);
            wsT[kk * WPAD + ch] = W[t];
        }
        __syncthreads();

        ull acc0[8], acc1[8];
#pragma unroll
        for (int i = 0; i < 8; ++i) { acc0[i] = 0ULL; acc1[i] = 0ULL; }

        const float* xrow = xs + (ngrp * 8) * DH;
#pragma unroll 4
        for (int kk4 = 0; kk4 < DH; kk4 += 4) {
            float4 xv[8];
#pragma unroll
            for (int i = 0; i < 8; ++i)
                xv[i] = *(const float4*)(xrow + i * DH + kk4);   // broadcast LDS.128
#pragma unroll
            for (int u = 0; u < 4; ++u) {
                ulonglong2 wp = *(const ulonglong2*)(wsT + (kk4 + u) * WPAD + c0);
#pragma unroll
                for (int i = 0; i < 8; ++i) {
                    float xs1 = (u == 0) ? xv[i].x : (u == 1) ? xv[i].y
                              : (u == 2) ? xv[i].z : xv[i].w;
                    ull xx = pk2(xs1, xs1);
                    acc0[i] = ffma2(xx, wp.x, acc0[i]);
                    acc1[i] = ffma2(xx, wp.y, acc1[i]);
                }
            }
        }

        float4 bias = *(const float4*)(Blist[w] + c0);
        float* O = Olist[w];
#pragma unroll
        for (int i = 0; i < 8; ++i) {
            int n = node0 + ngrp * 8 + i;
            if (n < NN) {
                float2 a = upk2(acc0[i]), b = upk2(acc1[i]);
                float4 o = make_float4(a.x + bias.x, a.y + bias.y, b.x + bias.z, b.y + bias.w);
                *(float4*)(O + (size_t)n * DH + c0) = o;
            }
        }
    }
}

// ---------------- qWe precompute (R13-validated): block per node ------------------
__global__ void qwe_kernel(const float* __restrict__ We) {
    __shared__ float qs[DH];
    const int n = blockIdx.x;
    const int tid = threadIdx.x;
    if (tid < DH) qs[tid] = g_q[(size_t)n * DH + tid];
    __syncthreads();
    const int h = tid >> 5, j = tid & 31;
    float acc = 0.f;
#pragma unroll
    for (int c = 0; c < CH; ++c)
        acc += qs[h * CH + c] * We[(h * CH + c) * DE + j];   // coalesced in j
    g_qwe[((size_t)n * NH + h) * DE + j] = acc;
}

// ---------------- CSR build (once per call) ---------------------------------------
__global__ void csr_zero_kernel() {
    int i = blockIdx.x * blockDim.x + threadIdx.x;
    if (i < NN) { g_deg[i] = 0; g_fill[i] = 0; }
}
__global__ void csr_hist_kernel(const int* __restrict__ eidx) {
    int i = blockIdx.x * blockDim.x + threadIdx.x;
    if (i < EE) atomicAdd(&g_deg[eidx[EE + i]], 1);
}
__global__ void csr_scan_kernel() {
    __shared__ int sh[1024];
    __shared__ int carry;
    const int tid = threadIdx.x;
    if (tid == 0) carry = 0;
    __syncthreads();
    for (int base = 0; base < NN; base += 1024) {
        int v = (base + tid < NN) ? g_deg[base + tid] : 0;
        sh[tid] = v;
        __syncthreads();
        for (int off = 1; off < 1024; off <<= 1) {
            int t = (tid >= off) ? sh[tid - off] : 0;
            __syncthreads();
            sh[tid] += t;
            __syncthreads();
        }
        if (base + tid < NN) g_rowptr[base + tid] = carry + sh[tid] - v;
        __syncthreads();
        if (tid == 0) carry += sh[1023];
        __syncthreads();
    }
    if (tid == 0) g_rowptr[NN] = carry;   // == EE
}
__global__ void csr_scatter_kernel(const int* __restrict__ eidx) {
    int i = blockIdx.x * blockDim.x + threadIdx.x;
    if (i >= EE) return;
    int dst = eidx[EE + i];
    int pos = g_rowptr[dst] + atomicAdd(&g_fill[dst], 1);
    g_eperm[pos] = i;
}

// ---------------- fused flash edge kernel (warp per destination) ------------------
// One pass per edge: logit (q·k + qWe·ef), online-rescaled softmax, message accum.
// Lanes: h2 = lane>>2 (head), q = lane&3. q[d], qWe[d] loop-invariant per segment.
__global__ void edgeC_flash(const int* __restrict__ eidx, const float* __restrict__ ef,
                            const float* __restrict__ We,
                            float* __restrict__ outp, int apply_gelu) {
    const int gw = (blockIdx.x * 256 + threadIdx.x) >> 5;
    const int lane = threadIdx.x & 31;
    if (gw >= NN) return;
    const int d = gw;
    const int p0 = g_rowptr[d];
    const int deg = g_rowptr[d + 1] - p0;
    const int h2 = lane >> 2, q = lane & 3;

    float4 acc = make_float4(0.f, 0.f, 0.f, 0.f);
    float wef[8];
#pragma unroll
    for (int t = 0; t < 8; ++t) wef[t] = 0.f;

    if (deg > 0) {
        // segment-invariant: q row (lane's 4 chans) + qWe chunk (head h2, dims q*8..+8)
        const float4 q4 = *(const float4*)(g_q + (size_t)d * DH + lane * 4);
        const float* qwrow = g_qwe + ((size_t)d * NH + h2) * DE + q * 8;
        const float4 qa = *(const float4*)qwrow;
        const float4 qb = *(const float4*)(qwrow + 4);

        int eL = -1, srcL = -1;
        if (lane < deg) { eL = g_eperm[p0 + lane]; srcL = eidx[eL]; }

        float m = -FLT_MAX, s = 0.f;
        for (int i = 0; i < deg; ++i) {
            int e, src;
            if (i < 32) {
                e = __shfl_sync(0xffffffffu, eL, i);
                src = __shfl_sync(0xffffffffu, srcL, i);
            } else {
                e = g_eperm[p0 + i];
                src = eidx[e];
            }
            float4 k4 = *(const float4*)(g_k + (size_t)src * DH + lane * 4);
            float4 v4 = *(const float4*)(g_v + (size_t)src * DH + lane * 4);
            float4 f0 = *(const float4*)(ef + (size_t)e * DE + q * 8);
            float4 f1 = *(const float4*)(ef + (size_t)e * DE + q * 8 + 4);

            // per-lane partial logit: q·k (4 chans) + qWe·ef (8 dims)
            float r = q4.x * k4.x + q4.y * k4.y + q4.z * k4.z + q4.w * k4.w
                    + qa.x * f0.x + qa.y * f0.y + qa.z * f0.z + qa.w * f0.w
                    + qb.x * f1.x + qb.y * f1.y + qb.z * f1.z + qb.w * f1.w;
            r += __shfl_xor_sync(0xffffffffu, r, 1);
            r += __shfl_xor_sync(0xffffffffu, r, 2);   // quad allreduce -> head logit
            r *= 0.25f;                                 // / sqrt(C=16)
            if (q == 0) g_raw[(size_t)e * NH + h2] = r;

            // online softmax rescale (replicated within quad)
            float nm = fmaxf(m, r);
            float sc = __expf(m - nm);
            float p  = __expf(r - nm);
            m = nm;
            s = s * sc + p;
            acc.x = acc.x * sc + p * v4.x;
            acc.y = acc.y * sc + p * v4.y;
            acc.z = acc.z * sc + p * v4.z;
            acc.w = acc.w * sc + p * v4.w;
            wef[0] = wef[0] * sc + p * f0.x; wef[1] = wef[1] * sc + p * f0.y;
            wef[2] = wef[2] * sc + p * f0.z; wef[3] = wef[3] * sc + p * f0.w;
            wef[4] = wef[4] * sc + p * f1.x; wef[5] = wef[5] * sc + p * f1.y;
            wef[6] = wef[6] * sc + p * f1.z; wef[7] = wef[7] * sc + p * f1.w;
        }

        // normalize once (reference: / (sum + 1e-16))
        float inv = 1.f / (s + 1e-16f);
        acc.x *= inv; acc.y *= inv; acc.z *= inv; acc.w *= inv;
#pragma unroll
        for (int t = 0; t < 8; ++t) wef[t] *= inv;

        if (q == 0) {                         // stats for alphaB
            g_m[(size_t)d * NH + h2] = m;
            g_s[(size_t)d * NH + h2] = s;
        }

        // epilogue GEMM (R13-validated): acc[ch] += Σ_j We[ch][j] * wef_full[h2][j]
        const int qbase = lane & ~3;
#pragma unroll
        for (int t = 0; t < 4; ++t) {
            float w0 = __shfl_sync(0xffffffffu, wef[0], qbase + t);
            float w1 = __shfl_sync(0xffffffffu, wef[1], qbase + t);
            float w2 = __shfl_sync(0xffffffffu, wef[2], qbase + t);
            float w3 = __shfl_sync(0xffffffffu, wef[3], qbase + t);
            float w4 = __shfl_sync(0xffffffffu, wef[4], qbase + t);
            float w5 = __shfl_sync(0xffffffffu, wef[5], qbase + t);
            float w6 = __shfl_sync(0xffffffffu, wef[6], qbase + t);
            float w7 = __shfl_sync(0xffffffffu, wef[7], qbase + t);
#pragma unroll
            for (int cc = 0; cc < 4; ++cc) {
                const float4* wr = (const float4*)(We + (size_t)(lane * 4 + cc) * DE + t * 8);
                float4 a0 = wr[0], a1 = wr[1];
                float sum = a0.x * w0 + a0.y * w1 + a0.z * w2 + a0.w * w3
                          + a1.x * w4 + a1.y * w5 + a1.z * w6 + a1.w * w7;
                if (cc == 0) acc.x += sum;
                else if (cc == 1) acc.y += sum;
                else if (cc == 2) acc.z += sum;
                else acc.w += sum;
            }
        }
    }

    // skip connection + optional exact-erf GELU, direct to layer output
    float4 skip = *(const float4*)(g_agg + (size_t)d * DH + lane * 4);
    acc.x += skip.x; acc.y += skip.y; acc.z += skip.z; acc.w += skip.w;
    if (apply_gelu) {
        acc.x *= normcdff(acc.x);
        acc.y *= normcdff(acc.y);
        acc.z *= normcdff(acc.z);
        acc.w *= normcdff(acc.w);
    }
    *(float4*)(outp + (size_t)d * DH + lane * 4) = acc;
}

// ---------------- alpha conversion: alpha = exp(raw - m[dst,h]) / (s + 1e-16) -----
__global__ void alphaB_kernel(const int* __restrict__ eidx, float* __restrict__ alpha_out) {
    int gt = blockIdx.x * blockDim.x + threadIdx.x;
    if (gt >= EE * NH) return;
    int e = gt >> 3, h = gt & 7;
    int dst = eidx[EE + e];
    float m = g_m[(size_t)dst * NH + h];
    float s = g_s[(size_t)dst * NH + h];
    alpha_out[gt] = __expf(g_raw[gt] - m) / (s + 1e-16f);
}

// ---------------- launch ----------------------------------------------------------
extern "C" void kernel_launch(void* const* d_in, const int* in_sizes, int n_in,
                              void* d_out, int out_size) {
    const float* x   = (const float*)d_in[0];
    const float* ef  = (const float*)d_in[1];
    const float* Wq  = (const float*)d_in[2];
    const float* bq  = (const float*)d_in[3];
    const float* Wk  = (const float*)d_in[4];
    const float* bk  = (const float*)d_in[5];
    const float* Wv  = (const float*)d_in[6];
    const float* bv  = (const float*)d_in[7];
    const float* We  = (const float*)d_in[8];
    const float* Ws  = (const float*)d_in[9];
    const float* bs  = (const float*)d_in[10];
    const int* eidx  = (const int*)d_in[11];
    float* out = (float*)d_out;

    cudaFuncSetAttribute(proj_kernel, cudaFuncAttributeMaxDynamicSharedMemorySize, PROJ_SMEM);
    float* feat = nullptr;
    cudaGetSymbolAddress((void**)&feat, g_feat);

    const int nproj = (NN + BN - 1) / BN;

    // CSR build: once per call, reused by all 4 layers
    csr_zero_kernel<<<(NN + 255) / 256, 256>>>();
    csr_hist_kernel<<<(EE + 255) / 256, 256>>>(eidx);
    csr_scan_kernel<<<1, 1024>>>();
    csr_scatter_kernel<<<(EE + 255) / 256, 256>>>(eidx);

    for (int l = 0; l < 4; ++l) {
        const float* hin = (l == 0) ? x : feat;
        size_t off2 = (size_t)l * DH * DH;
        size_t offb = (size_t)l * DH;
        size_t offe = (size_t)l * DH * DE;

        proj_kernel<<<nproj, PROJ_THREADS, PROJ_SMEM>>>(hin,
            Wq + off2, bq + offb, Wk + off2, bk + offb,
            Wv + off2, bv + offb, Ws + off2, bs + offb);
        qwe_kernel<<<NN, 256>>>(We + offe);
        edgeC_flash<<<(NN * 32 + 255) / 256, 256>>>(eidx, ef, We + offe,
            (l == 3) ? out : feat, (l < 3) ? 1 : 0);
        alphaB_kernel<<<(EE * NH) / 256, 256>>>(eidx,
            out + (size_t)NN * DH + (size_t)l * EE * NH);
    }
}